// round 3
// baseline (speedup 1.0000x reference)
#include <cuda_runtime.h>
#include <math.h>

// ---------------------------------------------------------------------------
// Problem constants (fixed by reference)
// ---------------------------------------------------------------------------
#define BATCH    2
#define SEQLEN   1024
#define DMODEL   1024
#define DINNER   2048
#define DTRANK   64
#define DSTATE   16
#define DCONV    4
#define NROWS    (BATCH*SEQLEN)          // 2048
#define XDBL_W   (DTRANK + 2*DSTATE)     // 96

// ---------------------------------------------------------------------------
// Scratch (static __device__ arrays; no allocations anywhere)
// ---------------------------------------------------------------------------
__device__ float g_xn   [NROWS * DMODEL];      // 8 MB  layernorm output
__device__ float g_xz   [NROWS * 2*DINNER];    // 32 MB in_proj output (u_raw | z)
__device__ float g_u    [NROWS * DINNER];      // 16 MB conv+silu output
__device__ float g_xdbl [NROWS * XDBL_W];      // 0.75 MB (dt | B | C)
__device__ float g_delta[NROWS * DINNER];      // 16 MB softplus(dt_proj)
__device__ float g_yg   [NROWS * DINNER];      // 16 MB gated scan output

// ---------------------------------------------------------------------------
// helpers
// ---------------------------------------------------------------------------
__device__ __forceinline__ float softplus_f(float x) {
    return fmaxf(x, 0.f) + log1pf(__expf(-fabsf(x)));
}
__device__ __forceinline__ float silu_f(float x) {
    return x * (1.f / (1.f + __expf(-x)));
}

__device__ __forceinline__ float block_reduce_sum(float v, float* scratch) {
    __syncthreads();                       // protect scratch reuse across calls
    int lane = threadIdx.x & 31, wid = threadIdx.x >> 5;
#pragma unroll
    for (int o = 16; o > 0; o >>= 1) v += __shfl_down_sync(0xffffffffu, v, o);
    if (lane == 0) scratch[wid] = v;
    __syncthreads();
    if (wid == 0) {
        v = (lane < 8) ? scratch[lane] : 0.f;
#pragma unroll
        for (int o = 4; o > 0; o >>= 1) v += __shfl_down_sync(0xffffffffu, v, o);
        if (lane == 0) scratch[0] = v;
    }
    __syncthreads();
    return scratch[0];
}

// ---------------------------------------------------------------------------
// 1) LayerNorm: one block per row (2048 rows x 1024 cols), 256 threads
// ---------------------------------------------------------------------------
__global__ __launch_bounds__(256)
void ln_kernel(const float* __restrict__ x, const float* __restrict__ gamma,
               const float* __restrict__ beta, float* __restrict__ out) {
    __shared__ float scratch[8];
    const int row = blockIdx.x;
    const int tid = threadIdx.x;
    const float4 v = reinterpret_cast<const float4*>(x + row * DMODEL)[tid];

    float s  = v.x + v.y + v.z + v.w;
    float mu = block_reduce_sum(s, scratch) * (1.f / DMODEL);

    float dx0 = v.x - mu, dx1 = v.y - mu, dx2 = v.z - mu, dx3 = v.w - mu;
    float ss  = dx0*dx0 + dx1*dx1 + dx2*dx2 + dx3*dx3;
    float var = block_reduce_sum(ss, scratch) * (1.f / DMODEL);
    float r   = rsqrtf(var + 1e-5f);

    const float4 g = reinterpret_cast<const float4*>(gamma)[tid];
    const float4 b = reinterpret_cast<const float4*>(beta)[tid];
    float4 o;
    o.x = dx0 * r * g.x + b.x;
    o.y = dx1 * r * g.y + b.y;
    o.z = dx2 * r * g.z + b.z;
    o.w = dx3 * r * g.w + b.w;
    reinterpret_cast<float4*>(out + row * DMODEL)[tid] = o;
}

// ---------------------------------------------------------------------------
// 2) Generic SGEMM-NT:  C[M,N] = A[M,K] * B[N,K]^T   (both K-contiguous)
//    EPI: 0 = store, 1 = softplus(acc + bias[col]), 2 = acc + res[row*ldc+col]
// ---------------------------------------------------------------------------
template<int BM, int BN, int BK, int TM, int TN, int EPI>
__global__ __launch_bounds__(256)
void sgemm_nt(const float* __restrict__ A, int lda,
              const float* __restrict__ B, int ldb,
              float* __restrict__ C, int ldc,
              int K, const float* __restrict__ extra) {
    static_assert((BM/TM)*(BN/TN) == 256, "256 threads");
    __shared__ float As[BK][BM + 4];
    __shared__ float Bs[BK][BN + 4];

    const int tid   = threadIdx.x;
    const int mBase = blockIdx.y * BM;
    const int nBase = blockIdx.x * BN;

    constexpr int KV        = BK / 4;
    const int aRow          = tid / KV;
    const int aCol          = (tid % KV) * 4;
    constexpr int rowStride = 256 / KV;

    const int tCol = tid % (BN / TN);
    const int tRow = tid / (BN / TN);

    float acc[TM][TN] = {};
    const float* Ag = A + mBase * lda;
    const float* Bg = B + nBase * ldb;

    for (int k0 = 0; k0 < K; k0 += BK) {
#pragma unroll
        for (int r = aRow; r < BM; r += rowStride) {
            float4 v = *reinterpret_cast<const float4*>(&Ag[r * lda + k0 + aCol]);
            As[aCol + 0][r] = v.x; As[aCol + 1][r] = v.y;
            As[aCol + 2][r] = v.z; As[aCol + 3][r] = v.w;
        }
#pragma unroll
        for (int r = aRow; r < BN; r += rowStride) {
            float4 v = *reinterpret_cast<const float4*>(&Bg[r * ldb + k0 + aCol]);
            Bs[aCol + 0][r] = v.x; Bs[aCol + 1][r] = v.y;
            Bs[aCol + 2][r] = v.z; Bs[aCol + 3][r] = v.w;
        }
        __syncthreads();

#pragma unroll
        for (int kk = 0; kk < BK; ++kk) {
            float regM[TM], regN[TN];
#pragma unroll
            for (int i = 0; i < TM; ++i) regM[i] = As[kk][tRow * TM + i];
#pragma unroll
            for (int j = 0; j < TN; ++j) regN[j] = Bs[kk][tCol * TN + j];
#pragma unroll
            for (int i = 0; i < TM; ++i)
#pragma unroll
                for (int j = 0; j < TN; ++j)
                    acc[i][j] = fmaf(regM[i], regN[j], acc[i][j]);
        }
        __syncthreads();
    }

#pragma unroll
    for (int i = 0; i < TM; ++i) {
        const int row = mBase + tRow * TM + i;
#pragma unroll
        for (int j = 0; j < TN; ++j) {
            const int col = nBase + tCol * TN + j;
            float v = acc[i][j];
            if (EPI == 1)      v = softplus_f(v + extra[col]);
            else if (EPI == 2) v = v + extra[row * ldc + col];
            C[row * ldc + col] = v;
        }
    }
}

// ---------------------------------------------------------------------------
// 3) Causal depthwise conv (d_conv=4) + bias + SiLU
//    input: u_raw = xz[:, 0:DINNER] (row stride 2*DINNER), output: g_u
//    grid (DINNER/128, SEQLEN/64, BATCH), 128 threads
// ---------------------------------------------------------------------------
__global__ __launch_bounds__(128)
void dwconv_silu(const float* __restrict__ xz, const float* __restrict__ w,
                 const float* __restrict__ bias, float* __restrict__ u) {
    const int c  = blockIdx.x * 128 + threadIdx.x;
    const int b  = blockIdx.z;
    const int t0 = blockIdx.y * 64;
    const int base = b * SEQLEN;

    const float w0 = w[c*4+0], w1 = w[c*4+1], w2 = w[c*4+2], w3 = w[c*4+3];
    const float bb = bias[c];

    float xm3 = (t0 >= 3) ? xz[(base + t0 - 3) * (2*DINNER) + c] : 0.f;
    float xm2 = (t0 >= 2) ? xz[(base + t0 - 2) * (2*DINNER) + c] : 0.f;
    float xm1 = (t0 >= 1) ? xz[(base + t0 - 1) * (2*DINNER) + c] : 0.f;

#pragma unroll 4
    for (int t = t0; t < t0 + 64; ++t) {
        const float xc = xz[(base + t) * (2*DINNER) + c];
        float v = fmaf(w0, xm3, fmaf(w1, xm2, fmaf(w2, xm1, fmaf(w3, xc, bb))));
        u[(base + t) * DINNER + c] = silu_f(v);
        xm3 = xm2; xm2 = xm1; xm1 = xc;
    }
}

// ---------------------------------------------------------------------------
// 4) Selective scan, fused with +u*D_skip and SiLU gate.
//    Block = 32 channels of one batch. 256 threads:
//      tid <  128 : compute (4 warps; lane layout: s = lane&3 owns states
//                   [4s,4s+4), channel = warp*8 + lane>>2)
//      tid >= 128 : loaders (double-buffer 32-timestep tiles into smem)
// ---------------------------------------------------------------------------
#define SCAN_T 32
#define NCHUNK (SEQLEN / SCAN_T)

__device__ __forceinline__ void scan_load_chunk(
    float* dst, int lt, int rowBase, int t0, int cbase,
    const float* __restrict__ dlt_g, const float* __restrict__ u_g,
    const float* __restrict__ xz_g,  const float* __restrict__ xdbl_g) {
#pragma unroll
    for (int i = 0; i < 8; ++i) {
        const int idx  = lt + i * 128;        // 0..1023 float4 slots
        const int tile = idx >> 8;            // 0:delta 1:u 2:z 3:B|C
        const int j    = idx & 255;
        const int t    = j >> 3;
        const int c4   = (j & 7) << 2;
        const int row  = rowBase + t0 + t;
        const float* src;
        if (tile == 0)      src = dlt_g  + row * DINNER     + cbase + c4;
        else if (tile == 1) src = u_g    + row * DINNER     + cbase + c4;
        else if (tile == 2) src = xz_g   + row * (2*DINNER) + DINNER + cbase + c4;
        else                src = xdbl_g + row * XDBL_W     + DTRANK + c4;
        *reinterpret_cast<float4*>(dst + (tile * SCAN_T + t) * 32 + c4) =
            *reinterpret_cast<const float4*>(src);
    }
}

__global__ __launch_bounds__(256)
void scan_kernel(const float* __restrict__ dlt_g, const float* __restrict__ u_g,
                 const float* __restrict__ xz_g,  const float* __restrict__ xdbl_g,
                 const float* __restrict__ Alog,  const float* __restrict__ Dsk,
                 float* __restrict__ yg) {
    __shared__ __align__(16) float sm[2][4][SCAN_T][32];

    const int tid     = threadIdx.x;
    const int cbase   = blockIdx.x * 32;
    const int b       = blockIdx.y;
    const int rowBase = b * SEQLEN;
    const bool loader = (tid >= 128);

    // compute-thread state
    int s = 0, c = 0, c_local = 0;
    float A0 = 0, A1 = 0, A2 = 0, A3 = 0, dskip = 0;
    float h0 = 0, h1 = 0, h2 = 0, h3 = 0;

    if (loader) {
        scan_load_chunk(&sm[0][0][0][0], tid - 128, rowBase, 0, cbase,
                        dlt_g, u_g, xz_g, xdbl_g);
    } else {
        const int w = tid >> 5, l = tid & 31;
        s = l & 3;
        c_local = w * 8 + (l >> 2);
        c = cbase + c_local;
        A0 = -__expf(Alog[c * DSTATE + 4 * s + 0]);
        A1 = -__expf(Alog[c * DSTATE + 4 * s + 1]);
        A2 = -__expf(Alog[c * DSTATE + 4 * s + 2]);
        A3 = -__expf(Alog[c * DSTATE + 4 * s + 3]);
        dskip = Dsk[c];
    }
    __syncthreads();

    for (int k = 0; k < NCHUNK; ++k) {
        if (loader) {
            if (k + 1 < NCHUNK)
                scan_load_chunk(&sm[(k + 1) & 1][0][0][0], tid - 128, rowBase,
                                (k + 1) * SCAN_T, cbase, dlt_g, u_g, xz_g, xdbl_g);
        } else {
            const float* buf = &sm[k & 1][0][0][0];
            const int t0 = k * SCAN_T;
#pragma unroll 4
            for (int t = 0; t < SCAN_T; ++t) {
                const float dlt = buf[(0 * SCAN_T + t) * 32 + c_local];
                const float uu  = buf[(1 * SCAN_T + t) * 32 + c_local];
                const float zz  = buf[(2 * SCAN_T + t) * 32 + c_local];
                const float4 Bv = *reinterpret_cast<const float4*>(
                                      &buf[(3 * SCAN_T + t) * 32 + 4 * s]);
                const float4 Cv = *reinterpret_cast<const float4*>(
                                      &buf[(3 * SCAN_T + t) * 32 + 16 + 4 * s]);
                const float du = dlt * uu;
                h0 = fmaf(__expf(dlt * A0), h0, du * Bv.x);
                h1 = fmaf(__expf(dlt * A1), h1, du * Bv.y);
                h2 = fmaf(__expf(dlt * A2), h2, du * Bv.z);
                h3 = fmaf(__expf(dlt * A3), h3, du * Bv.w);
                float y = fmaf(h0, Cv.x, fmaf(h1, Cv.y, fmaf(h2, Cv.z, h3 * Cv.w)));
                y += __shfl_xor_sync(0xffffffffu, y, 1);
                y += __shfl_xor_sync(0xffffffffu, y, 2);
                if (s == 0) {
                    const float yy = fmaf(uu, dskip, y);
                    yg[(rowBase + t0 + t) * DINNER + c] = yy * silu_f(zz);
                }
            }
        }
        __syncthreads();
    }
}

// ---------------------------------------------------------------------------
// Host launcher (graph-capturable: kernel launches on default stream only)
// ---------------------------------------------------------------------------
extern "C" void kernel_launch(void* const* d_in, const int* in_sizes, int n_in,
                              void* d_out, int out_size) {
    const float* x      = (const float*)d_in[0];
    const float* ln_g   = (const float*)d_in[1];
    const float* ln_b   = (const float*)d_in[2];
    const float* in_w   = (const float*)d_in[3];   // [4096,1024]
    const float* conv_w = (const float*)d_in[4];   // [2048,1,4]
    const float* conv_b = (const float*)d_in[5];
    const float* xp_w   = (const float*)d_in[6];   // [96,2048]
    const float* dt_w   = (const float*)d_in[7];   // [2048,64]
    const float* dt_b   = (const float*)d_in[8];
    const float* A_log  = (const float*)d_in[9];   // [2048,16]
    const float* D_sk   = (const float*)d_in[10];
    const float* out_w  = (const float*)d_in[11];  // [1024,2048]
    float* out = (float*)d_out;

    float *xn, *xz, *u, *xdbl, *delta, *yg;
    cudaGetSymbolAddress((void**)&xn,    g_xn);
    cudaGetSymbolAddress((void**)&xz,    g_xz);
    cudaGetSymbolAddress((void**)&u,     g_u);
    cudaGetSymbolAddress((void**)&xdbl,  g_xdbl);
    cudaGetSymbolAddress((void**)&delta, g_delta);
    cudaGetSymbolAddress((void**)&yg,    g_yg);

    // 1) LayerNorm
    ln_kernel<<<NROWS, 256>>>(x, ln_g, ln_b, xn);

    // 2) in_proj: xz[2048,4096] = xn[2048,1024] @ in_w^T
    sgemm_nt<128,128,16,8,8,0><<<dim3(2*DINNER/128, NROWS/128), 256>>>(
        xn, DMODEL, in_w, DMODEL, xz, 2*DINNER, DMODEL, nullptr);

    // 3) depthwise conv + bias + SiLU  -> u
    dwconv_silu<<<dim3(DINNER/128, SEQLEN/64, BATCH), 128>>>(xz, conv_w, conv_b, u);

    // 4) x_proj: xdbl[2048,96] = u @ xp_w^T  (skinny-N config)
    sgemm_nt<64,32,32,4,2,0><<<dim3(XDBL_W/32, NROWS/64), 256>>>(
        u, DINNER, xp_w, DINNER, xdbl, XDBL_W, DINNER, nullptr);

    // 5) dt_proj + bias + softplus: delta[2048,2048]
    sgemm_nt<128,128,16,8,8,1><<<dim3(DINNER/128, NROWS/128), 256>>>(
        xdbl, XDBL_W, dt_w, DTRANK, delta, DINNER, DTRANK, dt_b);

    // 6) selective scan + D-skip + gate -> yg
    scan_kernel<<<dim3(DINNER/32, BATCH), 256>>>(delta, u, xz, xdbl, A_log, D_sk, yg);

    // 7) out_proj + residual: out[2048,1024] = yg @ out_w^T + x
    sgemm_nt<128,128,16,8,8,2><<<dim3(DMODEL/128, NROWS/128), 256>>>(
        yg, DINNER, out_w, DINNER, out, DMODEL, DINNER, x);
}

// round 4
// speedup vs baseline: 2.2219x; 2.2219x over previous
#include <cuda_runtime.h>
#include <math.h>

// ---------------------------------------------------------------------------
// Problem constants (fixed by reference)
// ---------------------------------------------------------------------------
#define BATCH    2
#define SEQLEN   1024
#define DMODEL   1024
#define DINNER   2048
#define DTRANK   64
#define DSTATE   16
#define DCONV    4
#define NROWS    (BATCH*SEQLEN)          // 2048
#define XDBL_W   (DTRANK + 2*DSTATE)     // 96
#define XPROJ_SPLITK 8

// ---------------------------------------------------------------------------
// Scratch (static __device__ arrays; no allocations anywhere)
// ---------------------------------------------------------------------------
__device__ float g_xn   [NROWS * DMODEL];              // layernorm output
__device__ float g_xz   [NROWS * 2*DINNER];            // in_proj output (u_raw | z)
__device__ float g_u    [NROWS * DINNER];              // conv+silu output
__device__ float g_xdbl [NROWS * XDBL_W];              // (dt | B | C)
__device__ float g_xdbl_part[XPROJ_SPLITK * NROWS * XDBL_W]; // split-K partials
__device__ float g_delta[NROWS * DINNER];              // softplus(dt_proj)
__device__ float g_yg   [NROWS * DINNER];              // gated scan output

// ---------------------------------------------------------------------------
// helpers
// ---------------------------------------------------------------------------
__device__ __forceinline__ float softplus_f(float x) {
    return fmaxf(x, 0.f) + log1pf(__expf(-fabsf(x)));
}
__device__ __forceinline__ float silu_f(float x) {
    return x * (1.f / (1.f + __expf(-x)));
}

__device__ __forceinline__ unsigned f2tf32(float x) {
    unsigned r;
    asm("cvt.rna.tf32.f32 %0, %1;" : "=r"(r) : "f"(x));
    return r;
}

__device__ __forceinline__ void mma_tf32(float c[4],
                                         unsigned a0, unsigned a1, unsigned a2, unsigned a3,
                                         unsigned b0, unsigned b1) {
    asm volatile(
        "mma.sync.aligned.m16n8k8.row.col.f32.tf32.tf32.f32 "
        "{%0,%1,%2,%3}, {%4,%5,%6,%7}, {%8,%9}, {%0,%1,%2,%3};"
        : "+f"(c[0]), "+f"(c[1]), "+f"(c[2]), "+f"(c[3])
        : "r"(a0), "r"(a1), "r"(a2), "r"(a3), "r"(b0), "r"(b1));
}

__device__ __forceinline__ void cp_async16(void* s, const void* g) {
    unsigned a = (unsigned)__cvta_generic_to_shared(s);
    asm volatile("cp.async.cg.shared.global [%0], [%1], 16;\n" :: "r"(a), "l"(g));
}
__device__ __forceinline__ void cp_commit() {
    asm volatile("cp.async.commit_group;\n");
}
__device__ __forceinline__ void cp_wait1() {
    asm volatile("cp.async.wait_group 1;\n");
}

__device__ __forceinline__ float block_reduce_sum(float v, float* scratch) {
    __syncthreads();
    int lane = threadIdx.x & 31, wid = threadIdx.x >> 5;
#pragma unroll
    for (int o = 16; o > 0; o >>= 1) v += __shfl_down_sync(0xffffffffu, v, o);
    if (lane == 0) scratch[wid] = v;
    __syncthreads();
    if (wid == 0) {
        v = (lane < 8) ? scratch[lane] : 0.f;
#pragma unroll
        for (int o = 4; o > 0; o >>= 1) v += __shfl_down_sync(0xffffffffu, v, o);
        if (lane == 0) scratch[0] = v;
    }
    __syncthreads();
    return scratch[0];
}

// ---------------------------------------------------------------------------
// 1) LayerNorm: one block per row (2048 rows x 1024 cols), 256 threads
// ---------------------------------------------------------------------------
__global__ __launch_bounds__(256)
void ln_kernel(const float* __restrict__ x, const float* __restrict__ gamma,
               const float* __restrict__ beta, float* __restrict__ out) {
    __shared__ float scratch[8];
    const int row = blockIdx.x;
    const int tid = threadIdx.x;
    const float4 v = reinterpret_cast<const float4*>(x + row * DMODEL)[tid];

    float s  = v.x + v.y + v.z + v.w;
    float mu = block_reduce_sum(s, scratch) * (1.f / DMODEL);

    float dx0 = v.x - mu, dx1 = v.y - mu, dx2 = v.z - mu, dx3 = v.w - mu;
    float ss  = dx0*dx0 + dx1*dx1 + dx2*dx2 + dx3*dx3;
    float var = block_reduce_sum(ss, scratch) * (1.f / DMODEL);
    float r   = rsqrtf(var + 1e-5f);

    const float4 g = reinterpret_cast<const float4*>(gamma)[tid];
    const float4 b = reinterpret_cast<const float4*>(beta)[tid];
    float4 o;
    o.x = dx0 * r * g.x + b.x;
    o.y = dx1 * r * g.y + b.y;
    o.z = dx2 * r * g.z + b.z;
    o.w = dx3 * r * g.w + b.w;
    reinterpret_cast<float4*>(out + row * DMODEL)[tid] = o;
}

// ---------------------------------------------------------------------------
// 2) tf32 tensor-core GEMM-NT:  C[M,N] = A[M,K] * B[N,K]^T  (K-contiguous)
//    256 threads = 8 warps tiled (BM/WM) x (BN/WN); warp tile WM x WN via
//    m16n8k8 tf32 mma.sync. cp.async double-buffered BK=16 tiles.
//    EPI: 0=store  1=softplus(acc+bias[n])  2=acc+extra[m*ldc+n] (residual)
//    SPLITK>1: grid.z slices K; block z writes C + z*partStride (EPI=0).
// ---------------------------------------------------------------------------
template<int BM, int BN, int WM, int WN, int EPI, int SPLITK>
__global__ __launch_bounds__(256)
void mma_gemm(const float* __restrict__ A, int lda,
              const float* __restrict__ B, int ldb,
              float* __restrict__ C, int ldc, int K,
              const float* __restrict__ extra, int partStride) {
    constexpr int BK = 16, BKP = 20;
    constexpr int MI = WM / 16, NI = WN / 8;
    constexpr int WROWS = BM / WM;
    static_assert(WROWS * (BN / WN) == 8, "8 warps");

    __shared__ float As[2][BM][BKP];
    __shared__ float Bs[2][BN][BKP];

    const int tid  = threadIdx.x;
    const int warp = tid >> 5, lane = tid & 31;
    const int g    = lane >> 2, tg = lane & 3;
    const int wm   = (warp % WROWS) * WM;
    const int wn   = (warp / WROWS) * WN;
    const int mBase = blockIdx.y * BM;
    const int nBase = blockIdx.x * BN;
    const int kTiles = K / BK / SPLITK;

    const float* Ag = A + mBase * lda + blockIdx.z * kTiles * BK;
    const float* Bg = B + nBase * ldb + blockIdx.z * kTiles * BK;

    float acc[MI][NI][4];
#pragma unroll
    for (int i = 0; i < MI; ++i)
#pragma unroll
        for (int j = 0; j < NI; ++j)
#pragma unroll
            for (int e = 0; e < 4; ++e) acc[i][j][e] = 0.f;

    auto loadTile = [&](int t, int buf) {
        const float* a = Ag + t * BK;
#pragma unroll
        for (int q = tid; q < BM * 4; q += 256) {
            int r = q >> 2, c = (q & 3) << 2;
            cp_async16(&As[buf][r][c], a + r * lda + c);
        }
        const float* b = Bg + t * BK;
#pragma unroll
        for (int q = tid; q < BN * 4; q += 256) {
            int r = q >> 2, c = (q & 3) << 2;
            cp_async16(&Bs[buf][r][c], b + r * ldb + c);
        }
        cp_commit();
    };

    loadTile(0, 0);
    int buf = 0;
    for (int t = 0; t < kTiles; ++t) {
        if (t + 1 < kTiles) loadTile(t + 1, buf ^ 1);
        else                cp_commit();          // empty group keeps count
        cp_wait1();
        __syncthreads();

#pragma unroll
        for (int ks = 0; ks < BK; ks += 8) {
            unsigned af[MI][4], bf[NI][2];
#pragma unroll
            for (int mi = 0; mi < MI; ++mi) {
                const int r = wm + mi * 16 + g;
                af[mi][0] = f2tf32(As[buf][r    ][ks + tg    ]);
                af[mi][1] = f2tf32(As[buf][r + 8][ks + tg    ]);
                af[mi][2] = f2tf32(As[buf][r    ][ks + tg + 4]);
                af[mi][3] = f2tf32(As[buf][r + 8][ks + tg + 4]);
            }
#pragma unroll
            for (int ni = 0; ni < NI; ++ni) {
                const int r = wn + ni * 8 + g;
                bf[ni][0] = f2tf32(Bs[buf][r][ks + tg    ]);
                bf[ni][1] = f2tf32(Bs[buf][r][ks + tg + 4]);
            }
#pragma unroll
            for (int mi = 0; mi < MI; ++mi)
#pragma unroll
                for (int ni = 0; ni < NI; ++ni)
                    mma_tf32(acc[mi][ni], af[mi][0], af[mi][1], af[mi][2], af[mi][3],
                             bf[ni][0], bf[ni][1]);
        }
        __syncthreads();
        buf ^= 1;
    }

    float* Cw = C + (SPLITK > 1 ? blockIdx.z * partStride : 0);
#pragma unroll
    for (int mi = 0; mi < MI; ++mi) {
#pragma unroll
        for (int ni = 0; ni < NI; ++ni) {
            const int m0 = mBase + wm + mi * 16 + g;
            const int n0 = nBase + wn + ni * 8 + 2 * tg;
#pragma unroll
            for (int half = 0; half < 2; ++half) {
                const int m = m0 + 8 * half;
                float v0 = acc[mi][ni][2 * half + 0];
                float v1 = acc[mi][ni][2 * half + 1];
                if (EPI == 1) {
                    v0 = softplus_f(v0 + extra[n0]);
                    v1 = softplus_f(v1 + extra[n0 + 1]);
                } else if (EPI == 2) {
                    v0 += extra[m * ldc + n0];
                    v1 += extra[m * ldc + n0 + 1];
                }
                float2 o; o.x = v0; o.y = v1;
                *reinterpret_cast<float2*>(&Cw[m * ldc + n0]) = o;
            }
        }
    }
}

// ---------------------------------------------------------------------------
// 2b) reduce split-K partials for x_proj
// ---------------------------------------------------------------------------
__global__ __launch_bounds__(256)
void reduce_xdbl(const float* __restrict__ part, float* __restrict__ out) {
    const int i = blockIdx.x * 256 + threadIdx.x;      // float4 index
    constexpr int N4 = NROWS * XDBL_W / 4;
    if (i >= N4) return;
    float4 s = reinterpret_cast<const float4*>(part)[i];
#pragma unroll
    for (int k = 1; k < XPROJ_SPLITK; ++k) {
        float4 v = reinterpret_cast<const float4*>(part + k * NROWS * XDBL_W)[i];
        s.x += v.x; s.y += v.y; s.z += v.z; s.w += v.w;
    }
    reinterpret_cast<float4*>(out)[i] = s;
}

// ---------------------------------------------------------------------------
// 3) Causal depthwise conv (d_conv=4) + bias + SiLU
// ---------------------------------------------------------------------------
__global__ __launch_bounds__(128)
void dwconv_silu(const float* __restrict__ xz, const float* __restrict__ w,
                 const float* __restrict__ bias, float* __restrict__ u) {
    const int c  = blockIdx.x * 128 + threadIdx.x;
    const int b  = blockIdx.z;
    const int t0 = blockIdx.y * 64;
    const int base = b * SEQLEN;

    const float w0 = w[c*4+0], w1 = w[c*4+1], w2 = w[c*4+2], w3 = w[c*4+3];
    const float bb = bias[c];

    float xm3 = (t0 >= 3) ? xz[(base + t0 - 3) * (2*DINNER) + c] : 0.f;
    float xm2 = (t0 >= 2) ? xz[(base + t0 - 2) * (2*DINNER) + c] : 0.f;
    float xm1 = (t0 >= 1) ? xz[(base + t0 - 1) * (2*DINNER) + c] : 0.f;

#pragma unroll 4
    for (int t = t0; t < t0 + 64; ++t) {
        const float xc = xz[(base + t) * (2*DINNER) + c];
        float v = fmaf(w0, xm3, fmaf(w1, xm2, fmaf(w2, xm1, fmaf(w3, xc, bb))));
        u[(base + t) * DINNER + c] = silu_f(v);
        xm3 = xm2; xm2 = xm1; xm1 = xc;
    }
}

// ---------------------------------------------------------------------------
// 4) Selective scan, fused with +u*D_skip and SiLU gate.
// ---------------------------------------------------------------------------
#define SCAN_T 32
#define NCHUNK (SEQLEN / SCAN_T)

__device__ __forceinline__ void scan_load_chunk(
    float* dst, int lt, int rowBase, int t0, int cbase,
    const float* __restrict__ dlt_g, const float* __restrict__ u_g,
    const float* __restrict__ xz_g,  const float* __restrict__ xdbl_g) {
#pragma unroll
    for (int i = 0; i < 8; ++i) {
        const int idx  = lt + i * 128;        // 0..1023 float4 slots
        const int tile = idx >> 8;            // 0:delta 1:u 2:z 3:B|C
        const int j    = idx & 255;
        const int t    = j >> 3;
        const int c4   = (j & 7) << 2;
        const int row  = rowBase + t0 + t;
        const float* src;
        if (tile == 0)      src = dlt_g  + row * DINNER     + cbase + c4;
        else if (tile == 1) src = u_g    + row * DINNER     + cbase + c4;
        else if (tile == 2) src = xz_g   + row * (2*DINNER) + DINNER + cbase + c4;
        else                src = xdbl_g + row * XDBL_W     + DTRANK + c4;
        *reinterpret_cast<float4*>(dst + (tile * SCAN_T + t) * 32 + c4) =
            *reinterpret_cast<const float4*>(src);
    }
}

__global__ __launch_bounds__(256)
void scan_kernel(const float* __restrict__ dlt_g, const float* __restrict__ u_g,
                 const float* __restrict__ xz_g,  const float* __restrict__ xdbl_g,
                 const float* __restrict__ Alog,  const float* __restrict__ Dsk,
                 float* __restrict__ yg) {
    __shared__ __align__(16) float sm[2][4][SCAN_T][32];

    const int tid     = threadIdx.x;
    const int cbase   = blockIdx.x * 32;
    const int b       = blockIdx.y;
    const int rowBase = b * SEQLEN;
    const bool loader = (tid >= 128);

    int s = 0, c = 0, c_local = 0;
    float A0 = 0, A1 = 0, A2 = 0, A3 = 0, dskip = 0;
    float h0 = 0, h1 = 0, h2 = 0, h3 = 0;

    if (loader) {
        scan_load_chunk(&sm[0][0][0][0], tid - 128, rowBase, 0, cbase,
                        dlt_g, u_g, xz_g, xdbl_g);
    } else {
        const int w = tid >> 5, l = tid & 31;
        s = l & 3;
        c_local = w * 8 + (l >> 2);
        c = cbase + c_local;
        A0 = -__expf(Alog[c * DSTATE + 4 * s + 0]);
        A1 = -__expf(Alog[c * DSTATE + 4 * s + 1]);
        A2 = -__expf(Alog[c * DSTATE + 4 * s + 2]);
        A3 = -__expf(Alog[c * DSTATE + 4 * s + 3]);
        dskip = Dsk[c];
    }
    __syncthreads();

    for (int k = 0; k < NCHUNK; ++k) {
        if (loader) {
            if (k + 1 < NCHUNK)
                scan_load_chunk(&sm[(k + 1) & 1][0][0][0], tid - 128, rowBase,
                                (k + 1) * SCAN_T, cbase, dlt_g, u_g, xz_g, xdbl_g);
        } else {
            const float* buf = &sm[k & 1][0][0][0];
            const int t0 = k * SCAN_T;
#pragma unroll 4
            for (int t = 0; t < SCAN_T; ++t) {
                const float dlt = buf[(0 * SCAN_T + t) * 32 + c_local];
                const float uu  = buf[(1 * SCAN_T + t) * 32 + c_local];
                const float zz  = buf[(2 * SCAN_T + t) * 32 + c_local];
                const float4 Bv = *reinterpret_cast<const float4*>(
                                      &buf[(3 * SCAN_T + t) * 32 + 4 * s]);
                const float4 Cv = *reinterpret_cast<const float4*>(
                                      &buf[(3 * SCAN_T + t) * 32 + 16 + 4 * s]);
                const float du = dlt * uu;
                h0 = fmaf(__expf(dlt * A0), h0, du * Bv.x);
                h1 = fmaf(__expf(dlt * A1), h1, du * Bv.y);
                h2 = fmaf(__expf(dlt * A2), h2, du * Bv.z);
                h3 = fmaf(__expf(dlt * A3), h3, du * Bv.w);
                float y = fmaf(h0, Cv.x, fmaf(h1, Cv.y, fmaf(h2, Cv.z, h3 * Cv.w)));
                y += __shfl_xor_sync(0xffffffffu, y, 1);
                y += __shfl_xor_sync(0xffffffffu, y, 2);
                if (s == 0) {
                    const float yy = fmaf(uu, dskip, y);
                    yg[(rowBase + t0 + t) * DINNER + c] = yy * silu_f(zz);
                }
            }
        }
        __syncthreads();
    }
}

// ---------------------------------------------------------------------------
// Host launcher (graph-capturable: kernel launches on default stream only)
// ---------------------------------------------------------------------------
extern "C" void kernel_launch(void* const* d_in, const int* in_sizes, int n_in,
                              void* d_out, int out_size) {
    const float* x      = (const float*)d_in[0];
    const float* ln_g   = (const float*)d_in[1];
    const float* ln_b   = (const float*)d_in[2];
    const float* in_w   = (const float*)d_in[3];   // [4096,1024]
    const float* conv_w = (const float*)d_in[4];   // [2048,1,4]
    const float* conv_b = (const float*)d_in[5];
    const float* xp_w   = (const float*)d_in[6];   // [96,2048]
    const float* dt_w   = (const float*)d_in[7];   // [2048,64]
    const float* dt_b   = (const float*)d_in[8];
    const float* A_log  = (const float*)d_in[9];   // [2048,16]
    const float* D_sk   = (const float*)d_in[10];
    const float* out_w  = (const float*)d_in[11];  // [1024,2048]
    float* out = (float*)d_out;

    float *xn, *xz, *u, *xdbl, *xdblp, *delta, *yg;
    cudaGetSymbolAddress((void**)&xn,    g_xn);
    cudaGetSymbolAddress((void**)&xz,    g_xz);
    cudaGetSymbolAddress((void**)&u,     g_u);
    cudaGetSymbolAddress((void**)&xdbl,  g_xdbl);
    cudaGetSymbolAddress((void**)&xdblp, g_xdbl_part);
    cudaGetSymbolAddress((void**)&delta, g_delta);
    cudaGetSymbolAddress((void**)&yg,    g_yg);

    // 1) LayerNorm
    ln_kernel<<<NROWS, 256>>>(x, ln_g, ln_b, xn);

    // 2) in_proj: xz[2048,4096] = xn[2048,1024] @ in_w^T   (tf32 MMA)
    mma_gemm<128,128,64,32,0,1><<<dim3(2*DINNER/128, NROWS/128, 1), 256>>>(
        xn, DMODEL, in_w, DMODEL, xz, 2*DINNER, DMODEL, nullptr, 0);

    // 3) depthwise conv + bias + SiLU  -> u
    dwconv_silu<<<dim3(DINNER/128, SEQLEN/64, BATCH), 128>>>(xz, conv_w, conv_b, u);

    // 4) x_proj: xdbl[2048,96] = u @ xp_w^T   (tf32 MMA, split-K 8 + reduce)
    mma_gemm<128,96,64,24,0,XPROJ_SPLITK>
        <<<dim3(1, NROWS/128, XPROJ_SPLITK), 256>>>(
        u, DINNER, xp_w, DINNER, xdblp, XDBL_W, DINNER, nullptr, NROWS * XDBL_W);
    reduce_xdbl<<<(NROWS*XDBL_W/4 + 255)/256, 256>>>(xdblp, xdbl);

    // 5) dt_proj + bias + softplus: delta[2048,2048]   (tf32 MMA)
    mma_gemm<128,128,64,32,1,1><<<dim3(DINNER/128, NROWS/128, 1), 256>>>(
        xdbl, XDBL_W, dt_w, DTRANK, delta, DINNER, DTRANK, dt_b, 0);

    // 6) selective scan + D-skip + gate -> yg
    scan_kernel<<<dim3(DINNER/32, BATCH), 256>>>(delta, u, xz, xdbl, A_log, D_sk, yg);

    // 7) out_proj + residual: out[2048,1024] = yg @ out_w^T + x   (tf32 MMA)
    mma_gemm<128,128,64,32,2,1><<<dim3(DMODEL/128, NROWS/128, 1), 256>>>(
        yg, DINNER, out_w, DINNER, out, DMODEL, DINNER, x, 0);
}